// round 15
// baseline (speedup 1.0000x reference)
#include <cuda_runtime.h>
#include <cuda_fp16.h>
#include <math.h>
#include <stdint.h>

#define BATCH 8
#define HW    4096
#define LCTX  1024
#define EMB   512

typedef __half h16;

// blocked layout: [rowblk][kblk][128x64 swizzled]; 16KB per block
#define BLK_ELEMS 8192
#define BLK_BYTES 16384
#define NSTAGE 3
#define GEMM_SMEM (NSTAGE * 2 * BLK_BYTES)   // 98304

// ---------------- device scratch ----------------
__device__ __align__(128) float g_bq[EMB];
__device__ __align__(128) float g_u[EMB];          // wk·bq
__device__ __align__(128) float g_bias2[EMB];      // po2·wv_b
__device__ __align__(128) float g_rsum[BATCH * HW];
__device__ __align__(128) float g_cvec[BATCH * LCTX];

__device__ __align__(128) h16 g_wqT0_h[EMB*EMB];   // wq^T [f][e]
__device__ __align__(128) h16 g_piT_h [EMB*EMB];   // pi^T [c][e]
__device__ __align__(128) h16 g_WqCF_h[EMB*EMB];   // Wq_eff [c'][f]
__device__ __align__(128) h16 g_wkN_h [EMB*EMB];   // wk natural [c][f]
__device__ __align__(128) h16 g_wvN_h [EMB*EMB];   // wv natural [c][e]
__device__ __align__(128) h16 g_po_h[EMB*2*EMB];   // [o][k] Kt=1024
__device__ __align__(128) h16 g_M1_h [EMB*EMB];    // [c'][c]
__device__ __align__(128) h16 g_M2_h [EMB*EMB];    // [o][c]

__device__ __align__(128) h16 g_Z_h[(long)BATCH*HW*EMB];      // input^T [b][p][c]
__device__ __align__(128) h16 g_ctxT_h[(long)BATCH*LCTX*EMB]; // [b][l][c]
__device__ __align__(128) h16 g_K2_h[(long)BATCH*LCTX*EMB];   // K' [b][l][c']
__device__ __align__(128) h16 g_E_h[(long)BATCH*HW*LCTX];     // unnormalized exp(S)
__device__ __align__(128) h16 g_W2_h[(long)BATCH*EMB*LCTX];   // [b][o][l]

// ---------------- helpers ----------------
__device__ __forceinline__ uint32_t smem_u32(const void* p) {
    uint32_t r;
    asm("{ .reg .u64 t; cvta.to.shared.u64 t, %1; cvt.u32.u64 %0, t; }" : "=r"(r) : "l"(p));
    return r;
}
__device__ __forceinline__ void mbar_init(uint32_t a, uint32_t c) {
    asm volatile("mbarrier.init.shared.b64 [%0], %1;" :: "r"(a), "r"(c) : "memory");
}
__device__ __forceinline__ void mbar_expect(uint32_t a, uint32_t bytes) {
    asm volatile("mbarrier.arrive.expect_tx.shared.b64 _, [%0], %1;" :: "r"(a), "r"(bytes) : "memory");
}
__device__ __forceinline__ void mbar_wait(uint32_t a, uint32_t par) {
    asm volatile(
        "{\n\t.reg .pred P1;\n\tW%=:\n\t"
        "mbarrier.try_wait.parity.acquire.cta.shared::cta.b64 P1, [%0], %1, 0x989680;\n\t"
        "@P1 bra D%=;\n\tbra W%=;\n\tD%=:\n\t}" :: "r"(a), "r"(par) : "memory");
}
__device__ __forceinline__ void bulk_g2s(uint32_t dst, const void* src, uint32_t bytes, uint32_t bar) {
    asm volatile("cp.async.bulk.shared::cluster.global.mbarrier::complete_tx::bytes [%0], [%1], %2, [%3];"
                 :: "r"(dst), "l"(src), "r"(bytes), "r"(bar) : "memory");
}
__device__ __forceinline__ void ldsm_x4(uint32_t (&r)[4], uint32_t addr) {
    asm volatile("ldmatrix.sync.aligned.m8n8.x4.shared.b16 {%0,%1,%2,%3}, [%4];"
                 : "=r"(r[0]), "=r"(r[1]), "=r"(r[2]), "=r"(r[3]) : "r"(addr));
}
__device__ __forceinline__ void mma16816(float (&d)[4], const uint32_t (&a)[4],
                                         uint32_t b0, uint32_t b1) {
    asm volatile(
        "mma.sync.aligned.m16n8k16.row.col.f32.f16.f16.f32 "
        "{%0,%1,%2,%3}, {%4,%5,%6,%7}, {%8,%9}, {%0,%1,%2,%3};"
        : "+f"(d[0]), "+f"(d[1]), "+f"(d[2]), "+f"(d[3])
        : "r"(a[0]), "r"(a[1]), "r"(a[2]), "r"(a[3]), "r"(b0), "r"(b1));
}
__device__ __forceinline__ uint32_t pack2(h16 a, h16 b) {
    return (uint32_t)__half_as_ushort(a) | ((uint32_t)__half_as_ushort(b) << 16);
}
__device__ __forceinline__ long blk_off(int row, int k, int Kt) {
    long blk = (long)(row >> 7) * (Kt >> 6) + (k >> 6);
    uint32_t off = (uint32_t)((row & 127) * 128 + (k & 63) * 2);
    off ^= (off >> 3) & 0x70;
    return blk * BLK_ELEMS + (off >> 1);
}
__device__ __forceinline__ uint32_t swz_row(int r, int kbyte) {
    uint32_t o = (uint32_t)(r * 128 + kbyte);
    return o ^ ((o >> 3) & 0x70);
}

// ---------------- multi-job blocked fp16 GEMM ----------------
// epiMode 0, outMode 0: fp32 write alpha*acc + biasM[m] (+biasN[n])
// epiMode 0, outMode 1: fp16 blocked write alpha*acc + biasM[m] + biasN[n]
// epiMode 0, outMode 3: fp32 accumulate acc / biasN[b*HW + n]
// epiMode 1: Eh = exp(alpha*(acc + biasN[b*LCTX + n])); row sums atomically into Cf[b*HW + m]
struct Job {
    const h16 *Ah, *Bh;
    float* Cf; h16* Ch;
    const float *biasM, *biasN;
    long sA, sB, sC;
    int KtA, KtB, ldKtC;
    int K;
    float alpha;
    int gx, gy;
    int ctaEnd;
    int outMode, epiMode;
};
struct JobPack { Job j[4]; };

__global__ void __launch_bounds__(256, 2)
gemm_multi(JobPack P, int njobs)
{
    extern __shared__ __align__(128) char smem[];
    __shared__ __align__(8) uint64_t barsto[NSTAGE];

    int jid = 0, base = 0;
    for (int q = 0; q < njobs; q++) {
        if ((int)blockIdx.x < P.j[q].ctaEnd) { jid = q; base = q ? P.j[q - 1].ctaEnd : 0; break; }
    }
    const Job jb = P.j[jid];
    const int t = (int)blockIdx.x - base;
    const int bx = t % jb.gx;
    const int by = (t / jb.gx) % jb.gy;
    const int b  = t / (jb.gx * jb.gy);

    const int tid = threadIdx.x, wid = tid >> 5, lane = tid & 31;
    const int m0 = by * 128, n0 = bx * 128;
    const int wm = (wid & 3) * 32;
    const int wn = (wid >> 2) * 64;

    const h16* pAh = jb.Ah + (long)b * jb.sA + (long)(m0 >> 7) * (jb.KtA >> 6) * BLK_ELEMS;
    const h16* pBh = jb.Bh + (long)b * jb.sB + (long)(n0 >> 7) * (jb.KtB >> 6) * BLK_ELEMS;

    const uint32_t s_base = smem_u32(smem);
    const uint32_t bar0 = smem_u32(barsto);
    const int nch = jb.K >> 6;

    auto issue = [&](int c) {
        const int s = c % NSTAGE;
        const uint32_t sb = s_base + (uint32_t)s * (2 * BLK_BYTES);
        const uint32_t bar = bar0 + (uint32_t)s * 8;
        mbar_expect(bar, 2 * BLK_BYTES);
        bulk_g2s(sb,             pAh + (long)c * BLK_ELEMS, BLK_BYTES, bar);
        bulk_g2s(sb + BLK_BYTES, pBh + (long)c * BLK_ELEMS, BLK_BYTES, bar);
    };

    if (tid == 0) {
        for (int s = 0; s < NSTAGE; s++) mbar_init(bar0 + s * 8, 1);
        asm volatile("fence.proxy.async.shared::cta;" ::: "memory");
        const int pre = nch < NSTAGE ? nch : NSTAGE;
        for (int c = 0; c < pre; c++) issue(c);
    }
    __syncthreads();

    float acc[2][8][4];
#pragma unroll
    for (int i = 0; i < 2; i++)
#pragma unroll
        for (int j = 0; j < 8; j++)
#pragma unroll
            for (int q = 0; q < 4; q++) acc[i][j][q] = 0.f;

    const int lrow = lane & 15;
    const int lkby = ((lane >> 4) * 8) * 2;

    for (int c = 0; c < nch; c++) {
        const int s = c % NSTAGE;
        mbar_wait(bar0 + s * 8, (uint32_t)((c / NSTAGE) & 1));
        const uint32_t sb = s_base + (uint32_t)s * (2 * BLK_BYTES);

#pragma unroll
        for (int ks = 0; ks < 4; ks++) {
            const int kb = ks * 32 + lkby;
            uint32_t ah[2][4];
#pragma unroll
            for (int i = 0; i < 2; i++)
                ldsm_x4(ah[i], sb + swz_row(wm + i * 16 + lrow, kb));
            uint32_t bh[4][4];
#pragma unroll
            for (int jj = 0; jj < 4; jj++)
                ldsm_x4(bh[jj], sb + BLK_BYTES + swz_row(wn + jj * 16 + lrow, kb));
#pragma unroll
            for (int i = 0; i < 2; i++)
#pragma unroll
                for (int j = 0; j < 8; j++) {
                    const int jj = j >> 1, sel = j & 1;
                    mma16816(acc[i][j], ah[i], bh[jj][sel], bh[jj][sel + 2]);
                }
        }
        __syncthreads();
        if (tid == 0 && c + NSTAGE < nch) issue(c + NSTAGE);
    }

    // ---------------- epilogue ----------------
    const int mrow = m0 + wm + (lane >> 2);
    const int ncol0 = n0 + wn + 2 * (lane & 3);

    if (jb.epiMode == 1) {
        h16* ch = jb.Ch + (long)b * jb.sC;
        const float* cv = jb.biasN + (long)b * LCTX;
        float rs[2][2] = {{0.f, 0.f}, {0.f, 0.f}};
#pragma unroll
        for (int i = 0; i < 2; i++) {
            const int m = mrow + i * 16;
#pragma unroll
            for (int j = 0; j < 8; j++) {
                const int n = ncol0 + j * 8;
                const float c0 = cv[n], c1 = cv[n + 1];
                float e0 = __expf(jb.alpha * (acc[i][j][0] + c0));
                float e1 = __expf(jb.alpha * (acc[i][j][1] + c1));
                float e2 = __expf(jb.alpha * (acc[i][j][2] + c0));
                float e3 = __expf(jb.alpha * (acc[i][j][3] + c1));
                *reinterpret_cast<uint32_t*>(ch + blk_off(m,     n, jb.ldKtC)) =
                    pack2(__float2half_rn(e0), __float2half_rn(e1));
                *reinterpret_cast<uint32_t*>(ch + blk_off(m + 8, n, jb.ldKtC)) =
                    pack2(__float2half_rn(e2), __float2half_rn(e3));
                rs[i][0] += e0 + e1;
                rs[i][1] += e2 + e3;
            }
        }
#pragma unroll
        for (int i = 0; i < 2; i++)
#pragma unroll
            for (int hh = 0; hh < 2; hh++) {
                float v = rs[i][hh];
                v += __shfl_xor_sync(0xFFFFFFFFu, v, 1);
                v += __shfl_xor_sync(0xFFFFFFFFu, v, 2);
                rs[i][hh] = v;
            }
        if ((lane & 3) == 0) {
            float* sums = jb.Cf + (long)b * HW;
#pragma unroll
            for (int i = 0; i < 2; i++) {
                atomicAdd(&sums[mrow + i * 16],     rs[i][0]);
                atomicAdd(&sums[mrow + i * 16 + 8], rs[i][1]);
            }
        }
        return;
    }

    // epiMode 0
#pragma unroll
    for (int i = 0; i < 2; i++) {
        const int m = mrow + i * 16;
        const float bm0 = jb.biasM ? jb.biasM[m] : 0.f;
        const float bm8 = jb.biasM ? jb.biasM[m + 8] : 0.f;
#pragma unroll
        for (int j = 0; j < 8; j++) {
            const int n = ncol0 + j * 8;
            float v0, v1, v2, v3;
            if (jb.outMode == 3) {
                const float* sn = jb.biasN + (long)b * HW;
                const float s0 = 1.0f / sn[n], s1 = 1.0f / sn[n + 1];
                v0 = acc[i][j][0] * s0;
                v1 = acc[i][j][1] * s1;
                v2 = acc[i][j][2] * s0;
                v3 = acc[i][j][3] * s1;
            } else {
                const float bn0 = jb.biasN ? jb.biasN[n] : 0.f;
                const float bn1 = jb.biasN ? jb.biasN[n + 1] : 0.f;
                v0 = jb.alpha * acc[i][j][0] + bm0 + bn0;
                v1 = jb.alpha * acc[i][j][1] + bm0 + bn1;
                v2 = jb.alpha * acc[i][j][2] + bm8 + bn0;
                v3 = jb.alpha * acc[i][j][3] + bm8 + bn1;
            }
            if (jb.outMode == 0 || jb.outMode == 3) {
                float* co = jb.Cf + (long)b * jb.sC;
                float2* p0 = reinterpret_cast<float2*>(co + (long)m * jb.ldKtC + n);
                float2* p8 = reinterpret_cast<float2*>(co + (long)(m + 8) * jb.ldKtC + n);
                if (jb.outMode == 3) {
                    float2 o0 = *p0, o8 = *p8;
                    v0 += o0.x; v1 += o0.y; v2 += o8.x; v3 += o8.y;
                }
                *p0 = make_float2(v0, v1);
                *p8 = make_float2(v2, v3);
            } else {
                h16* ch = jb.Ch + (long)b * jb.sC;
                *reinterpret_cast<uint32_t*>(ch + blk_off(m,     n, jb.ldKtC)) =
                    pack2(__float2half_rn(v0), __float2half_rn(v1));
                *reinterpret_cast<uint32_t*>(ch + blk_off(m + 8, n, jb.ldKtC)) =
                    pack2(__float2half_rn(v2), __float2half_rn(v3));
            }
        }
    }
}

// ---------------- prep kernels ----------------

// blocks 0-1: bq fold; 2-3: bias2 = po2·wv_b; rest: zero rsum
__global__ void misc_prep_kernel(const float* __restrict__ pib, const float* __restrict__ wq,
                                 const float* __restrict__ wqb, float* __restrict__ bq,
                                 const float* __restrict__ po, const float* __restrict__ wvb,
                                 float* __restrict__ bias2, float* __restrict__ rsum)
{
    if (blockIdx.x < 2) {
        int f = blockIdx.x * 256 + threadIdx.x;
        float s = wqb[f];
        for (int e = 0; e < EMB; e++) s = fmaf(pib[e], wq[e * EMB + f], s);
        bq[f] = s;
        return;
    }
    if (blockIdx.x < 4) {
        int o = (blockIdx.x - 2) * 256 + threadIdx.x;
        float s = 0.f;
        for (int e = 0; e < EMB; e++) s = fmaf(po[(long)o * 2 * EMB + EMB + e], wvb[e], s);
        bias2[o] = s;
        return;
    }
    int i = (blockIdx.x - 4) * 256 + threadIdx.x;
    if (i < BATCH * HW) rsum[i] = 0.f;
}

// z 0: wq->wqT0 ; z 1: pi->piT (grid.x masked to 16) ; z 2..9: ctx transposes
// z 10: u[c] = sum_f wk[c,f]*bq[f] (warp-per-row; y<2 only)
struct WTJob { const float* s; h16* d; };
__global__ void trans_wctx_kernel(WTJob w0, WTJob w1,
                                  const float* __restrict__ ctx, h16* __restrict__ cth,
                                  const float* __restrict__ wk, const float* __restrict__ bq,
                                  float* __restrict__ u)
{
    __shared__ float tbuf[32][33];
    const int z = blockIdx.z;
    if (z == 10) {
        if (blockIdx.y >= 2) return;
        int row = ((blockIdx.y * 32 + blockIdx.x) * 8) + (threadIdx.y);
        int lane = threadIdx.x;
        float s = 0.f;
        for (int f = lane; f < EMB; f += 32) s = fmaf(wk[(long)row * EMB + f], bq[f], s);
#pragma unroll
        for (int d = 16; d > 0; d >>= 1) s += __shfl_xor_sync(0xFFFFFFFFu, s, d);
        if (lane == 0) u[row] = s;
        return;
    }
    const float* S;
    h16* D;
    int src_ld;
    if (z < 2) {
        if (blockIdx.x >= 16) return;
        WTJob w = (z == 0) ? w0 : w1;
        S = w.s; D = w.d; src_ld = EMB;
    } else {
        int b = z - 2;
        S = ctx + (long)b * EMB * LCTX;
        D = cth + (long)b * LCTX * EMB;
        src_ld = LCTX;
    }
    const int c0 = blockIdx.x * 32, r0 = blockIdx.y * 32;
    const int tx = threadIdx.x, ty = threadIdx.y;
#pragma unroll
    for (int k = 0; k < 4; k++)
        tbuf[ty + 8*k][tx] = S[(long)(r0 + ty + 8*k) * src_ld + c0 + tx];
    __syncthreads();
#pragma unroll
    for (int k = 0; k < 4; k++) {
        float x = tbuf[tx][ty + 8*k];
        D[blk_off(c0 + ty + 8*k, r0 + tx, EMB)] = __float2half_rn(x);
    }
}

__global__ void trans_input_kernel(const float* __restrict__ src, h16* __restrict__ dh)
{
    __shared__ float tbuf[32][33];
    const float* S = src + (long)blockIdx.z * EMB * HW;
    h16* DH = dh + (long)blockIdx.z * HW * EMB;
    const int c0 = blockIdx.x * 32, r0 = blockIdx.y * 32;
    const int tx = threadIdx.x, ty = threadIdx.y;
#pragma unroll
    for (int k = 0; k < 4; k++)
        tbuf[ty + 8*k][tx] = S[(long)(r0 + ty + 8*k) * HW + c0 + tx];
    __syncthreads();
#pragma unroll
    for (int k = 0; k < 4; k++) {
        float x = tbuf[tx][ty + 8*k];
        DH[blk_off(c0 + ty + 8*k, r0 + tx, EMB)] = __float2half_rn(x);
    }
}

// blocks [0,256): po convert; [256,384): wkN; [384,512): wvN;
// blocks [512,1536): cvec[b][l] = sum_c cth[b][l][c]*u[c] (warp per row)
__global__ void convert_cvec_kernel(const float* __restrict__ po, h16* __restrict__ poh,
                                    const float* __restrict__ wk, h16* __restrict__ wkNh,
                                    const float* __restrict__ wv, h16* __restrict__ wvNh,
                                    const h16* __restrict__ cth, const float* __restrict__ u,
                                    float* __restrict__ cvec)
{
    const int bxi = blockIdx.x;
    if (bxi >= 512) {
        __shared__ float us[EMB];
        for (int i = threadIdx.x; i < EMB; i += 256) us[i] = u[i];
        __syncthreads();
        int idx = (bxi - 512) * 8 + (threadIdx.x >> 5);     // 0..8191
        int b = idx >> 10, l = idx & 1023;
        int lane = threadIdx.x & 31;
        const h16* base = cth + (long)b * LCTX * EMB;
        float s = 0.f;
        for (int c = lane; c < EMB; c += 32)
            s = fmaf(__half2float(base[blk_off(l, c, EMB)]), us[c], s);
#pragma unroll
        for (int d = 16; d > 0; d >>= 1) s += __shfl_xor_sync(0xFFFFFFFFu, s, d);
        if (lane == 0) cvec[idx] = s;
        return;
    }
    const float* src;
    h16* dst;
    int Kt, i;
    if (bxi < 256)      { src = po; dst = poh;  Kt = 2*EMB; i = bxi * 256 + threadIdx.x; }
    else if (bxi < 384) { src = wk; dst = wkNh; Kt = EMB;   i = (bxi - 256) * 256 + threadIdx.x; }
    else                { src = wv; dst = wvNh; Kt = EMB;   i = (bxi - 384) * 256 + threadIdx.x; }
    const int kt8 = Kt >> 3;
    const int row = i / kt8;
    const int kq = (i - row * kt8) << 3;
    const float4* s4 = reinterpret_cast<const float4*>(src + (long)row * Kt + kq);
    float4 x0 = s4[0], x1 = s4[1];
    uint4 o;
    o.x = pack2(__float2half_rn(x0.x), __float2half_rn(x0.y));
    o.y = pack2(__float2half_rn(x0.z), __float2half_rn(x0.w));
    o.z = pack2(__float2half_rn(x1.x), __float2half_rn(x1.y));
    o.w = pack2(__float2half_rn(x1.z), __float2half_rn(x1.w));
    *reinterpret_cast<uint4*>(dst + blk_off(row, kq, Kt)) = o;
}

// ---------------- launch ----------------
extern "C" void kernel_launch(void* const* d_in, const int* in_sizes, int n_in,
                              void* d_out, int out_size)
{
    const float* input      = (const float*)d_in[0];
    const float* context    = (const float*)d_in[1];
    const float* proj_in_w  = (const float*)d_in[2];
    const float* proj_in_b  = (const float*)d_in[3];
    const float* wq_w       = (const float*)d_in[4];
    const float* wq_b       = (const float*)d_in[5];
    const float* wk_w       = (const float*)d_in[6];
    const float* wk_b       = (const float*)d_in[7];
    const float* wv_w       = (const float*)d_in[8];
    const float* wv_b       = (const float*)d_in[9];
    const float* proj_out_w = (const float*)d_in[10];
    const float* proj_out_b = (const float*)d_in[11];
    float* out = (float*)d_out;
    (void)wk_b;   // l-independent constants cancel in softmax

    cudaFuncSetAttribute(gemm_multi, cudaFuncAttributeMaxDynamicSharedMemorySize, GEMM_SMEM);

    float *bq, *u, *bias2, *rsum, *cvec;
    h16 *wqT0h,*piTh,*WqCFh,*wkNh,*wvNh,*poh,*M1h,*M2h,*Zh,*cth,*K2h,*Eh,*W2h;
    cudaGetSymbolAddress((void**)&bq, g_bq);
    cudaGetSymbolAddress((void**)&u, g_u);
    cudaGetSymbolAddress((void**)&bias2, g_bias2);
    cudaGetSymbolAddress((void**)&rsum, g_rsum);
    cudaGetSymbolAddress((void**)&cvec, g_cvec);
    cudaGetSymbolAddress((void**)&wqT0h, g_wqT0_h);
    cudaGetSymbolAddress((void**)&piTh, g_piT_h);
    cudaGetSymbolAddress((void**)&WqCFh, g_WqCF_h);
    cudaGetSymbolAddress((void**)&wkNh, g_wkN_h);
    cudaGetSymbolAddress((void**)&wvNh, g_wvN_h);
    cudaGetSymbolAddress((void**)&poh, g_po_h);
    cudaGetSymbolAddress((void**)&M1h, g_M1_h);
    cudaGetSymbolAddress((void**)&M2h, g_M2_h);
    cudaGetSymbolAddress((void**)&Zh, g_Z_h);
    cudaGetSymbolAddress((void**)&cth, g_ctxT_h);
    cudaGetSymbolAddress((void**)&K2h, g_K2_h);
    cudaGetSymbolAddress((void**)&Eh, g_E_h);
    cudaGetSymbolAddress((void**)&W2h, g_W2_h);

    const float scale = 1.0f / sqrtf((float)EMB);
    dim3 tb(32, 8);

    // ---- prep (4 launches) ----
    misc_prep_kernel<<<4 + (BATCH*HW + 255)/256, 256>>>(proj_in_b, wq_w, wq_b, bq,
                                                        proj_out_w, wv_b, bias2, rsum);
    {
        WTJob w0{wq_w, wqT0h}, w1{proj_in_w, piTh};
        trans_wctx_kernel<<<dim3(32,16,11), tb>>>(w0, w1, context, cth, wk_w, bq, u);
    }
    trans_input_kernel<<<dim3(128,16,BATCH), tb>>>(input, Zh);
    convert_cvec_kernel<<<1536, 256>>>(proj_out_w, poh, wk_w, wkNh, wv_w, wvNh, cth, u, cvec);

    // ---- T1: {WqCF, M2} (32 CTAs) ----
    {
        JobPack P{};
        // WqCF[c'][f] = piT · wqT0^T  (contract e)
        P.j[0] = { piTh, wqT0h, nullptr, WqCFh, nullptr, nullptr,
                   0, 0, 0, EMB, EMB, EMB, EMB, 1.0f, 4, 4, 16, 1, 0 };
        // M2[o][c] = po2 · wvN^T  (contract e)
        P.j[1] = { poh + 8*BLK_ELEMS, wvNh, nullptr, M2h, nullptr, nullptr,
                   0, 0, 0, 2*EMB, EMB, EMB, EMB, 1.0f, 4, 4, 32, 1, 0 };
        gemm_multi<<<32, 256, GEMM_SMEM>>>(P, 2);
    }
    // ---- T2: M1[c'][c] = WqCF · wkN^T (contract f) (16 CTAs) ----
    {
        JobPack P{};
        P.j[0] = { WqCFh, wkNh, nullptr, M1h, nullptr, nullptr,
                   0, 0, 0, EMB, EMB, EMB, EMB, 1.0f, 4, 4, 16, 1, 0 };
        gemm_multi<<<16, 256, GEMM_SMEM>>>(P, 1);
    }
    // ---- G2: {out1, K' = ctx·M1^T, W2 = M2·ctx^T + bias2} (1536 CTAs) ----
    {
        JobPack P{};
        P.j[0] = { poh, Zh, out, nullptr, proj_out_b, nullptr,
                   0, (long)HW*EMB, (long)EMB*HW, 2*EMB, EMB, HW,
                   EMB, 1.0f, 32, 4, 1024, 0, 0 };
        P.j[1] = { cth, M1h, nullptr, K2h, nullptr, nullptr,
                   (long)LCTX*EMB, 0, (long)LCTX*EMB, EMB, EMB, EMB,
                   EMB, 1.0f, 4, 8, 1024 + 256, 1, 0 };
        P.j[2] = { M2h, cth, nullptr, W2h, bias2, nullptr,
                   0, (long)LCTX*EMB, (long)EMB*LCTX, EMB, EMB, LCTX,
                   EMB, 1.0f, 8, 4, 1024 + 512, 1, 0 };
        gemm_multi<<<1536, 256, GEMM_SMEM>>>(P, 3);
    }
    // ---- G4: E = exp(scale*(Z·K'^T + cvec[l])), rowsums -> rsum ----
    {
        JobPack P{};
        P.j[0] = { Zh, K2h, rsum, Eh, nullptr, cvec,
                   (long)HW*EMB, (long)LCTX*EMB, (long)HW*LCTX, EMB, EMB, LCTX,
                   EMB, scale, 8, 32, 2048, 1, 1 };
        gemm_multi<<<2048, 256, GEMM_SMEM>>>(P, 1);
    }
    // ---- G5: out2[o][p] = (W2 · E^T) / rsum[p], accumulate onto out ----
    {
        JobPack P{};
        P.j[0] = { W2h, Eh, out, nullptr, nullptr, rsum,
                   (long)EMB*LCTX, (long)HW*LCTX, (long)EMB*HW, LCTX, LCTX, HW,
                   LCTX, 1.0f, 32, 4, 1024, 3, 0 };
        gemm_multi<<<1024, 256, GEMM_SMEM>>>(P, 1);
    }
}

// round 16
// speedup vs baseline: 1.0707x; 1.0707x over previous
#include <cuda_runtime.h>
#include <cuda_fp16.h>
#include <math.h>
#include <stdint.h>

#define BATCH 8
#define HW    4096
#define LCTX  1024
#define EMB   512

typedef __half h16;

// blocked layout: [rowblk][kblk][128x64 swizzled]; 16KB per block
#define BLK_ELEMS 8192
#define BLK_BYTES 16384
#define NSTAGE 3
#define GEMM_SMEM (NSTAGE * 2 * BLK_BYTES)   // 98304

// ---------------- device scratch ----------------
__device__ __align__(128) float g_bq[EMB];
__device__ __align__(128) float g_rsum[BATCH * HW];
__device__ __align__(128) float g_cvec[BATCH * LCTX];

__device__ __align__(128) h16 g_wqT0_h[EMB*EMB];     // wq^T [f][e]
__device__ __align__(128) h16 g_piT_h [EMB*EMB];     // pi^T [c][e]
__device__ __align__(128) h16 g_WqCF_h[EMB*EMB];     // Wq_eff [c][f]
__device__ __align__(128) h16 g_wkT_h [EMB*EMB];     // [f][c]
__device__ __align__(128) h16 g_wvT_h [EMB*EMB];     // [e][c]
__device__ __align__(128) h16 g_po_h[EMB*2*EMB];     // [o][k] Kt=1024

__device__ __align__(128) h16 g_Z_h[(long)BATCH*HW*EMB];      // input^T [b][p][c]
__device__ __align__(128) h16 g_ctxT_h[(long)BATCH*LCTX*EMB]; // [b][l][c]
__device__ __align__(128) h16 g_K_h[(long)BATCH*LCTX*EMB];    // [b][l][f]
__device__ __align__(128) h16 g_V_h[(long)BATCH*LCTX*EMB];    // [b][l][e]
__device__ __align__(128) h16 g_K2_h[(long)BATCH*LCTX*EMB];   // K' [b][l][c]
__device__ __align__(128) h16 g_E_h[(long)BATCH*HW*LCTX];     // unnormalized exp(S)
__device__ __align__(128) h16 g_W2_h[(long)BATCH*EMB*LCTX];   // [b][o][l]

// ---------------- helpers ----------------
__device__ __forceinline__ uint32_t smem_u32(const void* p) {
    uint32_t r;
    asm("{ .reg .u64 t; cvta.to.shared.u64 t, %1; cvt.u32.u64 %0, t; }" : "=r"(r) : "l"(p));
    return r;
}
__device__ __forceinline__ void mbar_init(uint32_t a, uint32_t c) {
    asm volatile("mbarrier.init.shared.b64 [%0], %1;" :: "r"(a), "r"(c) : "memory");
}
__device__ __forceinline__ void mbar_expect(uint32_t a, uint32_t bytes) {
    asm volatile("mbarrier.arrive.expect_tx.shared.b64 _, [%0], %1;" :: "r"(a), "r"(bytes) : "memory");
}
__device__ __forceinline__ void mbar_wait(uint32_t a, uint32_t par) {
    asm volatile(
        "{\n\t.reg .pred P1;\n\tW%=:\n\t"
        "mbarrier.try_wait.parity.acquire.cta.shared::cta.b64 P1, [%0], %1, 0x989680;\n\t"
        "@P1 bra D%=;\n\tbra W%=;\n\tD%=:\n\t}" :: "r"(a), "r"(par) : "memory");
}
__device__ __forceinline__ void bulk_g2s(uint32_t dst, const void* src, uint32_t bytes, uint32_t bar) {
    asm volatile("cp.async.bulk.shared::cluster.global.mbarrier::complete_tx::bytes [%0], [%1], %2, [%3];"
                 :: "r"(dst), "l"(src), "r"(bytes), "r"(bar) : "memory");
}
__device__ __forceinline__ void ldsm_x4(uint32_t (&r)[4], uint32_t addr) {
    asm volatile("ldmatrix.sync.aligned.m8n8.x4.shared.b16 {%0,%1,%2,%3}, [%4];"
                 : "=r"(r[0]), "=r"(r[1]), "=r"(r[2]), "=r"(r[3]) : "r"(addr));
}
__device__ __forceinline__ void mma16816(float (&d)[4], const uint32_t (&a)[4],
                                         uint32_t b0, uint32_t b1) {
    asm volatile(
        "mma.sync.aligned.m16n8k16.row.col.f32.f16.f16.f32 "
        "{%0,%1,%2,%3}, {%4,%5,%6,%7}, {%8,%9}, {%0,%1,%2,%3};"
        : "+f"(d[0]), "+f"(d[1]), "+f"(d[2]), "+f"(d[3])
        : "r"(a[0]), "r"(a[1]), "r"(a[2]), "r"(a[3]), "r"(b0), "r"(b1));
}
__device__ __forceinline__ uint32_t pack2(h16 a, h16 b) {
    return (uint32_t)__half_as_ushort(a) | ((uint32_t)__half_as_ushort(b) << 16);
}
__device__ __forceinline__ long blk_off(int row, int k, int Kt) {
    long blk = (long)(row >> 7) * (Kt >> 6) + (k >> 6);
    uint32_t off = (uint32_t)((row & 127) * 128 + (k & 63) * 2);
    off ^= (off >> 3) & 0x70;
    return blk * BLK_ELEMS + (off >> 1);
}
__device__ __forceinline__ uint32_t swz_row(int r, int kbyte) {
    uint32_t o = (uint32_t)(r * 128 + kbyte);
    return o ^ ((o >> 3) & 0x70);
}

// ---------------- multi-job blocked fp16 GEMM ----------------
// epiMode 0, outMode 0: fp32 write alpha*acc + biasM[m] (+biasN[n])
// epiMode 0, outMode 1: fp16 blocked write alpha*acc + biasM[m] + biasN[n]
// epiMode 0, outMode 3: fp32 accumulate acc / biasN[b*HW + n]
// epiMode 1: Eh = exp(alpha*(acc + biasN[b*LCTX + n])); row sums atomically into Cf[b*HW + m]
// epiMode 2: fp16 blocked write (acc + biasN[n]); Cf[b*LCTX + m] += sum_n biasM[n]*v (atomics)
struct Job {
    const h16 *Ah, *Bh;
    float* Cf; h16* Ch;
    const float *biasM, *biasN;
    long sA, sB, sC;
    int KtA, KtB, ldKtC;
    int K;
    float alpha;
    int gx, gy;
    int ctaEnd;
    int outMode, epiMode;
};
struct JobPack { Job j[4]; };

__global__ void __launch_bounds__(256, 2)
gemm_multi(JobPack P, int njobs)
{
    extern __shared__ __align__(128) char smem[];
    __shared__ __align__(8) uint64_t barsto[NSTAGE];

    int jid = 0, base = 0;
    for (int q = 0; q < njobs; q++) {
        if ((int)blockIdx.x < P.j[q].ctaEnd) { jid = q; base = q ? P.j[q - 1].ctaEnd : 0; break; }
    }
    const Job jb = P.j[jid];
    const int t = (int)blockIdx.x - base;
    const int bx = t % jb.gx;
    const int by = (t / jb.gx) % jb.gy;
    const int b  = t / (jb.gx * jb.gy);

    const int tid = threadIdx.x, wid = tid >> 5, lane = tid & 31;
    const int m0 = by * 128, n0 = bx * 128;
    const int wm = (wid & 3) * 32;
    const int wn = (wid >> 2) * 64;

    const h16* pAh = jb.Ah + (long)b * jb.sA + (long)(m0 >> 7) * (jb.KtA >> 6) * BLK_ELEMS;
    const h16* pBh = jb.Bh + (long)b * jb.sB + (long)(n0 >> 7) * (jb.KtB >> 6) * BLK_ELEMS;

    const uint32_t s_base = smem_u32(smem);
    const uint32_t bar0 = smem_u32(barsto);
    const int nch = jb.K >> 6;

    auto issue = [&](int c) {
        const int s = c % NSTAGE;
        const uint32_t sb = s_base + (uint32_t)s * (2 * BLK_BYTES);
        const uint32_t bar = bar0 + (uint32_t)s * 8;
        mbar_expect(bar, 2 * BLK_BYTES);
        bulk_g2s(sb,             pAh + (long)c * BLK_ELEMS, BLK_BYTES, bar);
        bulk_g2s(sb + BLK_BYTES, pBh + (long)c * BLK_ELEMS, BLK_BYTES, bar);
    };

    if (tid == 0) {
        for (int s = 0; s < NSTAGE; s++) mbar_init(bar0 + s * 8, 1);
        asm volatile("fence.proxy.async.shared::cta;" ::: "memory");
        const int pre = nch < NSTAGE ? nch : NSTAGE;
        for (int c = 0; c < pre; c++) issue(c);
    }
    __syncthreads();

    float acc[2][8][4];
#pragma unroll
    for (int i = 0; i < 2; i++)
#pragma unroll
        for (int j = 0; j < 8; j++)
#pragma unroll
            for (int q = 0; q < 4; q++) acc[i][j][q] = 0.f;

    const int lrow = lane & 15;
    const int lkby = ((lane >> 4) * 8) * 2;

    for (int c = 0; c < nch; c++) {
        const int s = c % NSTAGE;
        mbar_wait(bar0 + s * 8, (uint32_t)((c / NSTAGE) & 1));
        const uint32_t sb = s_base + (uint32_t)s * (2 * BLK_BYTES);

#pragma unroll
        for (int ks = 0; ks < 4; ks++) {
            const int kb = ks * 32 + lkby;
            uint32_t ah[2][4];
#pragma unroll
            for (int i = 0; i < 2; i++)
                ldsm_x4(ah[i], sb + swz_row(wm + i * 16 + lrow, kb));
            uint32_t bh[4][4];
#pragma unroll
            for (int jj = 0; jj < 4; jj++)
                ldsm_x4(bh[jj], sb + BLK_BYTES + swz_row(wn + jj * 16 + lrow, kb));
#pragma unroll
            for (int i = 0; i < 2; i++)
#pragma unroll
                for (int j = 0; j < 8; j++) {
                    const int jj = j >> 1, sel = j & 1;
                    mma16816(acc[i][j], ah[i], bh[jj][sel], bh[jj][sel + 2]);
                }
        }
        __syncthreads();
        if (tid == 0 && c + NSTAGE < nch) issue(c + NSTAGE);
    }

    // ---------------- epilogue ----------------
    const int mrow = m0 + wm + (lane >> 2);
    const int ncol0 = n0 + wn + 2 * (lane & 3);

    if (jb.epiMode == 1) {
        h16* ch = jb.Ch + (long)b * jb.sC;
        const float* cv = jb.biasN + (long)b * LCTX;
        float rs[2][2] = {{0.f, 0.f}, {0.f, 0.f}};
#pragma unroll
        for (int i = 0; i < 2; i++) {
            const int m = mrow + i * 16;
#pragma unroll
            for (int j = 0; j < 8; j++) {
                const int n = ncol0 + j * 8;
                const float c0 = cv[n], c1 = cv[n + 1];
                float e0 = __expf(jb.alpha * (acc[i][j][0] + c0));
                float e1 = __expf(jb.alpha * (acc[i][j][1] + c1));
                float e2 = __expf(jb.alpha * (acc[i][j][2] + c0));
                float e3 = __expf(jb.alpha * (acc[i][j][3] + c1));
                *reinterpret_cast<uint32_t*>(ch + blk_off(m,     n, jb.ldKtC)) =
                    pack2(__float2half_rn(e0), __float2half_rn(e1));
                *reinterpret_cast<uint32_t*>(ch + blk_off(m + 8, n, jb.ldKtC)) =
                    pack2(__float2half_rn(e2), __float2half_rn(e3));
                rs[i][0] += e0 + e1;
                rs[i][1] += e2 + e3;
            }
        }
#pragma unroll
        for (int i = 0; i < 2; i++)
#pragma unroll
            for (int hh = 0; hh < 2; hh++) {
                float v = rs[i][hh];
                v += __shfl_xor_sync(0xFFFFFFFFu, v, 1);
                v += __shfl_xor_sync(0xFFFFFFFFu, v, 2);
                rs[i][hh] = v;
            }
        if ((lane & 3) == 0) {
            float* sums = jb.Cf + (long)b * HW;
#pragma unroll
            for (int i = 0; i < 2; i++) {
                atomicAdd(&sums[mrow + i * 16],     rs[i][0]);
                atomicAdd(&sums[mrow + i * 16 + 8], rs[i][1]);
            }
        }
        return;
    }

    if (jb.epiMode == 2) {
        h16* ch = jb.Ch + (long)b * jb.sC;
        float ws[2][2] = {{0.f, 0.f}, {0.f, 0.f}};
#pragma unroll
        for (int i = 0; i < 2; i++) {
            const int m = mrow + i * 16;
#pragma unroll
            for (int j = 0; j < 8; j++) {
                const int n = ncol0 + j * 8;
                const float bn0 = jb.biasN[n], bn1 = jb.biasN[n + 1];
                float v0 = acc[i][j][0] + bn0;
                float v1 = acc[i][j][1] + bn1;
                float v2 = acc[i][j][2] + bn0;
                float v3 = acc[i][j][3] + bn1;
                *reinterpret_cast<uint32_t*>(ch + blk_off(m,     n, jb.ldKtC)) =
                    pack2(__float2half_rn(v0), __float2half_rn(v1));
                *reinterpret_cast<uint32_t*>(ch + blk_off(m + 8, n, jb.ldKtC)) =
                    pack2(__float2half_rn(v2), __float2half_rn(v3));
                const float w0 = jb.biasM[n], w1 = jb.biasM[n + 1];
                ws[i][0] += w0 * v0 + w1 * v1;
                ws[i][1] += w0 * v2 + w1 * v3;
            }
        }
#pragma unroll
        for (int i = 0; i < 2; i++)
#pragma unroll
            for (int hh = 0; hh < 2; hh++) {
                float v = ws[i][hh];
                v += __shfl_xor_sync(0xFFFFFFFFu, v, 1);
                v += __shfl_xor_sync(0xFFFFFFFFu, v, 2);
                ws[i][hh] = v;
            }
        if ((lane & 3) == 0) {
            float* cv = jb.Cf + (long)b * LCTX;
#pragma unroll
            for (int i = 0; i < 2; i++) {
                atomicAdd(&cv[mrow + i * 16],     ws[i][0]);
                atomicAdd(&cv[mrow + i * 16 + 8], ws[i][1]);
            }
        }
        return;
    }

    // epiMode 0
#pragma unroll
    for (int i = 0; i < 2; i++) {
        const int m = mrow + i * 16;
        const float bm0 = jb.biasM ? jb.biasM[m] : 0.f;
        const float bm8 = jb.biasM ? jb.biasM[m + 8] : 0.f;
#pragma unroll
        for (int j = 0; j < 8; j++) {
            const int n = ncol0 + j * 8;
            float v0, v1, v2, v3;
            if (jb.outMode == 3) {
                const float* sn = jb.biasN + (long)b * HW;
                const float s0 = 1.0f / sn[n], s1 = 1.0f / sn[n + 1];
                v0 = acc[i][j][0] * s0;
                v1 = acc[i][j][1] * s1;
                v2 = acc[i][j][2] * s0;
                v3 = acc[i][j][3] * s1;
            } else {
                const float bn0 = jb.biasN ? jb.biasN[n] : 0.f;
                const float bn1 = jb.biasN ? jb.biasN[n + 1] : 0.f;
                v0 = jb.alpha * acc[i][j][0] + bm0 + bn0;
                v1 = jb.alpha * acc[i][j][1] + bm0 + bn1;
                v2 = jb.alpha * acc[i][j][2] + bm8 + bn0;
                v3 = jb.alpha * acc[i][j][3] + bm8 + bn1;
            }
            if (jb.outMode == 0 || jb.outMode == 3) {
                float* co = jb.Cf + (long)b * jb.sC;
                float2* p0 = reinterpret_cast<float2*>(co + (long)m * jb.ldKtC + n);
                float2* p8 = reinterpret_cast<float2*>(co + (long)(m + 8) * jb.ldKtC + n);
                if (jb.outMode == 3) {
                    float2 o0 = *p0, o8 = *p8;
                    v0 += o0.x; v1 += o0.y; v2 += o8.x; v3 += o8.y;
                }
                *p0 = make_float2(v0, v1);
                *p8 = make_float2(v2, v3);
            } else {
                h16* ch = jb.Ch + (long)b * jb.sC;
                *reinterpret_cast<uint32_t*>(ch + blk_off(m,     n, jb.ldKtC)) =
                    pack2(__float2half_rn(v0), __float2half_rn(v1));
                *reinterpret_cast<uint32_t*>(ch + blk_off(m + 8, n, jb.ldKtC)) =
                    pack2(__float2half_rn(v2), __float2half_rn(v3));
            }
        }
    }
}

// ---------------- prep kernels ----------------

// blocks 0-1: bq fold; rest: zero rsum + cvec
__global__ void misc_prep_kernel(const float* __restrict__ pib, const float* __restrict__ wq,
                                 const float* __restrict__ wqb, float* __restrict__ bq,
                                 float* __restrict__ rsum, float* __restrict__ cvec)
{
    if (blockIdx.x < 2) {
        int f = blockIdx.x * 256 + threadIdx.x;
        float s = wqb[f];
        for (int e = 0; e < EMB; e++) s = fmaf(pib[e], wq[e * EMB + f], s);
        bq[f] = s;
        return;
    }
    int i = (blockIdx.x - 2) * 256 + threadIdx.x;
    if (i < BATCH * HW) rsum[i] = 0.f;
    if (i < BATCH * LCTX) cvec[i] = 0.f;
}

// z 0..3 : 512x512 weight transposes (grid.x masked to 16)
// z 4..11: ctx batch transposes
struct WTJob { const float* s; h16* d; };
__global__ void trans_wctx_kernel(WTJob w0, WTJob w1, WTJob w2, WTJob w3,
                                  const float* __restrict__ ctx, h16* __restrict__ cth)
{
    __shared__ float tbuf[32][33];
    const int z = blockIdx.z;
    const float* S;
    h16* D;
    int src_ld;
    if (z < 4) {
        if (blockIdx.x >= 16) return;
        WTJob w = (z == 0) ? w0 : (z == 1) ? w1 : (z == 2) ? w2 : w3;
        S = w.s; D = w.d; src_ld = EMB;
    } else {
        int b = z - 4;
        S = ctx + (long)b * EMB * LCTX;
        D = cth + (long)b * LCTX * EMB;
        src_ld = LCTX;
    }
    const int c0 = blockIdx.x * 32, r0 = blockIdx.y * 32;
    const int tx = threadIdx.x, ty = threadIdx.y;
#pragma unroll
    for (int k = 0; k < 4; k++)
        tbuf[ty + 8*k][tx] = S[(long)(r0 + ty + 8*k) * src_ld + c0 + tx];
    __syncthreads();
#pragma unroll
    for (int k = 0; k < 4; k++) {
        float x = tbuf[tx][ty + 8*k];
        D[blk_off(c0 + ty + 8*k, r0 + tx, EMB)] = __float2half_rn(x);
    }
}

// z < BATCH: input batch transpose; z == BATCH: vectorized po convert (first 256 blocks)
__global__ void trans_input_po_kernel(const float* __restrict__ src, h16* __restrict__ dh,
                                      const float* __restrict__ po, h16* __restrict__ poh)
{
    if (blockIdx.z == BATCH) {
        const int bid = blockIdx.y * 128 + blockIdx.x;
        if (bid >= 256) return;
        const int tid = threadIdx.y * 32 + threadIdx.x;
        const int i = bid * 256 + tid;            // vec id over 65536 (= 512*1024/8)
        const int row = i >> 7;                   // / (1024/8)
        const int kq = (i & 127) << 3;
        const float4* s4 = reinterpret_cast<const float4*>(po + (long)row * (2*EMB) + kq);
        float4 x0 = s4[0], x1 = s4[1];
        uint4 o;
        o.x = pack2(__float2half_rn(x0.x), __float2half_rn(x0.y));
        o.y = pack2(__float2half_rn(x0.z), __float2half_rn(x0.w));
        o.z = pack2(__float2half_rn(x1.x), __float2half_rn(x1.y));
        o.w = pack2(__float2half_rn(x1.z), __float2half_rn(x1.w));
        *reinterpret_cast<uint4*>(poh + blk_off(row, kq, 2*EMB)) = o;
        return;
    }
    __shared__ float tbuf[32][33];
    const float* S = src + (long)blockIdx.z * EMB * HW;
    h16* DH = dh + (long)blockIdx.z * HW * EMB;
    const int c0 = blockIdx.x * 32, r0 = blockIdx.y * 32;
    const int tx = threadIdx.x, ty = threadIdx.y;
#pragma unroll
    for (int k = 0; k < 4; k++)
        tbuf[ty + 8*k][tx] = S[(long)(r0 + ty + 8*k) * HW + c0 + tx];
    __syncthreads();
#pragma unroll
    for (int k = 0; k < 4; k++) {
        float x = tbuf[tx][ty + 8*k];
        DH[blk_off(c0 + ty + 8*k, r0 + tx, EMB)] = __float2half_rn(x);
    }
}

// ---------------- launch ----------------
extern "C" void kernel_launch(void* const* d_in, const int* in_sizes, int n_in,
                              void* d_out, int out_size)
{
    const float* input      = (const float*)d_in[0];
    const float* context    = (const float*)d_in[1];
    const float* proj_in_w  = (const float*)d_in[2];
    const float* proj_in_b  = (const float*)d_in[3];
    const float* wq_w       = (const float*)d_in[4];
    const float* wq_b       = (const float*)d_in[5];
    const float* wk_w       = (const float*)d_in[6];
    const float* wk_b       = (const float*)d_in[7];
    const float* wv_w       = (const float*)d_in[8];
    const float* wv_b       = (const float*)d_in[9];
    const float* proj_out_w = (const float*)d_in[10];
    const float* proj_out_b = (const float*)d_in[11];
    float* out = (float*)d_out;

    cudaFuncSetAttribute(gemm_multi, cudaFuncAttributeMaxDynamicSharedMemorySize, GEMM_SMEM);

    float *bq, *rsum, *cvec;
    h16 *wqT0h,*piTh,*WqCFh,*wkTh,*wvTh,*poh,*Zh,*cth,*Kh,*Vh,*K2h,*Eh,*W2h;
    cudaGetSymbolAddress((void**)&bq, g_bq);
    cudaGetSymbolAddress((void**)&rsum, g_rsum);
    cudaGetSymbolAddress((void**)&cvec, g_cvec);
    cudaGetSymbolAddress((void**)&wqT0h, g_wqT0_h);
    cudaGetSymbolAddress((void**)&piTh, g_piT_h);
    cudaGetSymbolAddress((void**)&WqCFh, g_WqCF_h);
    cudaGetSymbolAddress((void**)&wkTh, g_wkT_h);
    cudaGetSymbolAddress((void**)&wvTh, g_wvT_h);
    cudaGetSymbolAddress((void**)&poh, g_po_h);
    cudaGetSymbolAddress((void**)&Zh, g_Z_h);
    cudaGetSymbolAddress((void**)&cth, g_ctxT_h);
    cudaGetSymbolAddress((void**)&Kh, g_K_h);
    cudaGetSymbolAddress((void**)&Vh, g_V_h);
    cudaGetSymbolAddress((void**)&K2h, g_K2_h);
    cudaGetSymbolAddress((void**)&Eh, g_E_h);
    cudaGetSymbolAddress((void**)&W2h, g_W2_h);

    const float scale = 1.0f / sqrtf((float)EMB);
    dim3 tb(32, 8);

    // ---- prep (3 launches) ----
    misc_prep_kernel<<<2 + (BATCH*HW + 255)/256, 256>>>(proj_in_b, wq_w, wq_b, bq, rsum, cvec);
    {
        WTJob w0{wq_w, wqT0h}, w1{proj_in_w, piTh}, w2{wk_w, wkTh}, w3{wv_w, wvTh};
        trans_wctx_kernel<<<dim3(32,16,12), tb>>>(w0, w1, w2, w3, context, cth);
    }
    trans_input_po_kernel<<<dim3(128,16,BATCH+1), tb>>>(input, Zh, proj_out_w, poh);

    // ---- G2: {out1, K(+cvec), V, WqCF fold} ----
    {
        JobPack P{};
        // out1[o][p] = po1 · Z^T + proj_out_b  (fp32 write)
        P.j[0] = { poh, Zh, out, nullptr, proj_out_b, nullptr,
                   0, (long)HW*EMB, (long)EMB*HW, 2*EMB, EMB, HW,
                   EMB, 1.0f, 32, 4, 1024, 0, 0 };
        // K[l][f] = ctx^T · wkT^T + wk_b ; cvec[l] += sum_f bq[f]*K[l][f]
        P.j[1] = { cth, wkTh, cvec, Kh, bq, wk_b,
                   (long)LCTX*EMB, 0, (long)LCTX*EMB, EMB, EMB, EMB,
                   EMB, 1.0f, 4, 8, 1024 + 256, 1, 2 };
        // V[l][e] = ctx^T · wvT^T + wv_b
        P.j[2] = { cth, wvTh, nullptr, Vh, nullptr, wv_b,
                   (long)LCTX*EMB, 0, (long)LCTX*EMB, EMB, EMB, EMB,
                   EMB, 1.0f, 4, 8, 1024 + 512, 1, 0 };
        // WqCF[c][f] = piT · wqT0^T
        P.j[3] = { piTh, wqT0h, nullptr, WqCFh, nullptr, nullptr,
                   0, 0, 0, EMB, EMB, EMB,
                   EMB, 1.0f, 4, 4, 1024 + 512 + 16, 1, 0 };
        gemm_multi<<<1024 + 512 + 16, 256, GEMM_SMEM>>>(P, 4);
    }
    // ---- G3: {K', W2} ----
    {
        JobPack P{};
        // K'[l][c] = K · WqCF^T
        P.j[0] = { Kh, WqCFh, nullptr, K2h, nullptr, nullptr,
                   (long)LCTX*EMB, 0, (long)LCTX*EMB, EMB, EMB, EMB,
                   EMB, 1.0f, 4, 8, 256, 1, 0 };
        // W2[o][l] = po2 · V^T
        P.j[1] = { poh + 8*BLK_ELEMS, Vh, nullptr, W2h, nullptr, nullptr,
                   0, (long)LCTX*EMB, (long)EMB*LCTX, 2*EMB, EMB, LCTX,
                   EMB, 1.0f, 8, 4, 256 + 256, 1, 0 };
        gemm_multi<<<512, 256, GEMM_SMEM>>>(P, 2);
    }
    // ---- G4: E = exp(scale*(Z·K'^T + cvec[l])), rowsums -> rsum ----
    {
        JobPack P{};
        P.j[0] = { Zh, K2h, rsum, Eh, nullptr, cvec,
                   (long)HW*EMB, (long)LCTX*EMB, (long)HW*LCTX, EMB, EMB, LCTX,
                   EMB, scale, 8, 32, 2048, 1, 1 };
        gemm_multi<<<2048, 256, GEMM_SMEM>>>(P, 1);
    }
    // ---- G5: out2[o][p] = (W2 · E^T) / rsum[p], accumulate onto out ----
    {
        JobPack P{};
        P.j[0] = { W2h, Eh, out, nullptr, nullptr, rsum,
                   (long)EMB*LCTX, (long)HW*LCTX, (long)EMB*HW, LCTX, LCTX, HW,
                   LCTX, 1.0f, 32, 4, 1024, 3, 0 };
        gemm_multi<<<1024, 256, GEMM_SMEM>>>(P, 1);
    }
}